// round 6
// baseline (speedup 1.0000x reference)
#include <cuda_runtime.h>
#include <math.h>

// Problem constants
#define Bsz 64
#define Lsz 24
#define Dsz 512
#define Hsz 512
#define NSLOT (Bsz*Lsz)   // 1536 node slots
#define UWLD 5120         // per-slot row: [u(2560) | w(2560)]
#define HCLD 1024         // per-slot row: [h(512) | c(512)]

// Static scratch (no allocations allowed)
__device__ __align__(16) float g_HC[NSLOT*HCLD];   // 6.3 MB
__device__ __align__(16) float g_UW[NSLOT*UWLD];   // 31.5 MB
__device__ __align__(16) float g_NH[Bsz*Hsz];      // merged-node h, compact per batch
__device__ float g_scores[Bsz*Lsz];
__device__ int   g_pos[Bsz*Lsz];                   // logical position -> slot
__device__ int   g_k[Bsz];                         // last merge position (-1 = none)
__device__ int   g_rowmap[Bsz];                    // slot to receive updated u/w (-1 = skip)

__device__ __forceinline__ float sigf(float x) { return 1.0f/(1.0f+expf(-x)); }

// Gate math for pair (slot l, slot r) at hidden dim t.
// v = u_l + w_r  (comp_b already folded into u during the GEMM)
__device__ __forceinline__ void pair_gates(int l, int r, int t, float& nh, float& nc) {
    const float* u = g_UW + (size_t)l*UWLD;
    const float* w = g_UW + (size_t)r*UWLD + 2560;
    float gi  = u[t]        + w[t];
    float gfl = u[512 + t]  + w[512 + t];
    float gfr = u[1024 + t] + w[1024 + t];
    float gu  = u[1536 + t] + w[1536 + t];
    float go  = u[2048 + t] + w[2048 + t];
    float cl  = g_HC[(size_t)l*HCLD + 512 + t];
    float cr  = g_HC[(size_t)r*HCLD + 512 + t];
    nc = cl*sigf(gfl + 1.0f) + cr*sigf(gfr + 1.0f) + tanhf(gu)*sigf(gi);
    nh = sigf(go)*tanhf(nc);
}

// ---------------------------------------------------------------------------
// Generic NT GEMM: C[m,n] = sum_k A[m,k]*B[n,k] (+bias), 64xBN tiles, K%16==0.
// DUAL: virtual B = [comp_W[:, :512] ; comp_W[:, 512:]] stacked (n<2560 -> Wl,
// else Wr), bias applied to first half only. rowmap: per-m output row (-1 skip).
// ---------------------------------------------------------------------------
template<int BN, bool DUAL>
__global__ void gemm_nt(const float* __restrict__ A, int lda,
                        const float* __restrict__ Bm, int ldb,
                        const float* __restrict__ bias,
                        float* __restrict__ C, int ldc,
                        int K,
                        const int* __restrict__ rowmap)
{
    constexpr int BM = 64, BK = 16;
    constexpr int NTH = BM*BN/16;   // 4x4 outputs per thread
    __shared__ float As[BK][BM];
    __shared__ float Bs[BK][BN];
    const int tid = threadIdx.x;
    const int m0 = blockIdx.y * BM;
    const int n0 = blockIdx.x * BN;
    const int tx = tid % (BN/4);
    const int ty = tid / (BN/4);
    float acc[4][4] = {};

    for (int k0 = 0; k0 < K; k0 += BK) {
        {   // load A tile (BM x BK), float4 along k, store transposed
            constexpr int NV = (BM*BK/4)/NTH;
            #pragma unroll
            for (int v = 0; v < NV; v++) {
                int idx = tid + v*NTH;
                int m  = idx % BM;
                int kq = idx / BM;
                float4 a = *(const float4*)(A + (size_t)(m0+m)*lda + k0 + kq*4);
                As[kq*4+0][m] = a.x; As[kq*4+1][m] = a.y;
                As[kq*4+2][m] = a.z; As[kq*4+3][m] = a.w;
            }
        }
        {   // load B tile (BN x BK)
            constexpr int NV = (BN*BK/4)/NTH;
            #pragma unroll
            for (int v = 0; v < NV; v++) {
                int idx = tid + v*NTH;
                int n  = idx % BN;
                int kq = idx / BN;
                int gn = n0 + n;
                const float* bp;
                if (DUAL)
                    bp = (gn < 2560) ? (Bm + (size_t)gn*1024 + k0 + kq*4)
                                     : (Bm + (size_t)(gn-2560)*1024 + 512 + k0 + kq*4);
                else
                    bp = Bm + (size_t)gn*ldb + k0 + kq*4;
                float4 bv = *(const float4*)bp;
                Bs[kq*4+0][n] = bv.x; Bs[kq*4+1][n] = bv.y;
                Bs[kq*4+2][n] = bv.z; Bs[kq*4+3][n] = bv.w;
            }
        }
        __syncthreads();
        #pragma unroll
        for (int k = 0; k < BK; k++) {
            float4 av = *(const float4*)&As[k][ty*4];
            float4 bv = *(const float4*)&Bs[k][tx*4];
            float am[4] = {av.x, av.y, av.z, av.w};
            float bn_[4] = {bv.x, bv.y, bv.z, bv.w};
            #pragma unroll
            for (int i2 = 0; i2 < 4; i2++)
                #pragma unroll
                for (int j2 = 0; j2 < 4; j2++)
                    acc[i2][j2] += am[i2]*bn_[j2];
        }
        __syncthreads();
    }

    #pragma unroll
    for (int i2 = 0; i2 < 4; i2++) {
        int m = m0 + ty*4 + i2;
        int orow = rowmap ? rowmap[m] : m;
        if (orow < 0) continue;
        int gn = n0 + tx*4;
        float b0 = 0.f, b1 = 0.f, b2 = 0.f, b3 = 0.f;
        if (bias) {
            if (!DUAL || gn < 2560) {   // 2560 % BN == 0 -> tile-uniform
                b0 = bias[gn]; b1 = bias[gn+1]; b2 = bias[gn+2]; b3 = bias[gn+3];
            }
        }
        float4 o;
        o.x = acc[i2][0] + b0; o.y = acc[i2][1] + b1;
        o.z = acc[i2][2] + b2; o.w = acc[i2][3] + b3;
        *(float4*)(C + (size_t)orow*ldc + gn) = o;
    }
}

// ---------------------------------------------------------------------------
__global__ void k_init_pos() {
    int i = blockIdx.x*blockDim.x + threadIdx.x;
    if (i < Bsz*Lsz) g_pos[i] = i;
}

// Iteration 0: score all 23 adjacent pairs (invalid ones are masked at argmax,
// matching the reference, which also computes them).
__global__ void k_score_all(const float* __restrict__ q) {
    int j = blockIdx.x, b = blockIdx.y;
    int l = g_pos[b*Lsz + j], r = g_pos[b*Lsz + j + 1];
    float part = 0.f;
    for (int t = threadIdx.x; t < 512; t += 256) {
        float nh, nc; pair_gates(l, r, t, nh, nc);
        part += nh * q[t];
    }
    __shared__ float red[8];
    #pragma unroll
    for (int o = 16; o; o >>= 1) part += __shfl_down_sync(0xffffffffu, part, o);
    if ((threadIdx.x & 31) == 0) red[threadIdx.x >> 5] = part;
    __syncthreads();
    if (threadIdx.x == 0) {
        float s = 0.f;
        #pragma unroll
        for (int w = 0; w < 8; w++) s += red[w];
        g_scores[b*Lsz + j] = s;
    }
}

// Fused per-iteration step: rescore the (<=2) pairs invalidated by last merge,
// argmax over valid pairs, merge at k (reusing left child's slot), shift the
// logical pos/scores lists, stage new_h for the u/w update GEMM.
__global__ void k_step(const float* __restrict__ q, const int* __restrict__ length, int iter) {
    int b = blockIdx.x;
    int tid = threadIdx.x;
    __shared__ float red[2][4];
    __shared__ int s_k;
    int nvalid = length[b] - 1 - iter;   // valid pair count this iteration

    if (iter > 0) {
        int kp = g_k[b];                 // previous merge position
        if (kp >= 0) {
            int half = tid >> 7;         // pair selector: kp-1 or kp
            int ht   = tid & 127;
            int jj = kp - 1 + half;
            bool act = (jj >= 0) && (jj < nvalid);  // only valid scores are ever read
            float part = 0.f;
            if (act) {
                int l = g_pos[b*Lsz + jj], r = g_pos[b*Lsz + jj + 1];
                #pragma unroll
                for (int s = 0; s < 4; s++) {
                    int t = ht + s*128;
                    float nh, nc; pair_gates(l, r, t, nh, nc);
                    part += nh * q[t];
                }
            }
            #pragma unroll
            for (int o = 16; o; o >>= 1) part += __shfl_down_sync(0xffffffffu, part, o);
            if ((ht & 31) == 0) red[half][ht >> 5] = part;
            __syncthreads();
            if (ht == 0 && act)
                g_scores[b*Lsz + jj] = red[half][0] + red[half][1] + red[half][2] + red[half][3];
        }
    }
    __syncthreads();

    // argmax with first-index tie-break (matches jnp.argmax)
    if (tid < 32) {
        float v = (tid < nvalid) ? g_scores[b*Lsz + tid] : -1e9f;
        int idx = tid;
        #pragma unroll
        for (int o = 16; o; o >>= 1) {
            float v2 = __shfl_down_sync(0xffffffffu, v, o);
            int  i2  = __shfl_down_sync(0xffffffffu, idx, o);
            if (v2 > v || (v2 == v && i2 < idx)) { v = v2; idx = i2; }
        }
        if (tid == 0) s_k = (nvalid > 0) ? idx : -1;
    }
    __syncthreads();
    int k = s_k;
    if (k < 0) {                                   // done==0: sequence frozen
        if (tid == 0) { g_rowmap[b] = -1; g_k[b] = -1; }
        return;
    }
    int l = g_pos[b*Lsz + k], r = g_pos[b*Lsz + k + 1];
    for (int t = tid; t < 512; t += 256) {
        float nh, nc; pair_gates(l, r, t, nh, nc);
        g_HC[(size_t)l*HCLD + t]       = nh;       // merged node reuses left slot
        g_HC[(size_t)l*HCLD + 512 + t] = nc;
        g_NH[b*512 + t] = nh;                      // staged for update GEMM
    }
    __syncthreads();
    if (tid == 0) {
        g_rowmap[b] = l;
        g_k[b] = k;
        // left-shift logical lists past the removed right child; score[k]/[k-1]
        // become stale but are rescored next iteration iff still valid.
        for (int j = k + 1; j < Lsz - 1; j++) {
            g_pos[b*Lsz + j]    = g_pos[b*Lsz + j + 1];
            g_scores[b*Lsz + j] = g_scores[b*Lsz + j + 1];
        }
    }
}

__global__ void k_output(float* __restrict__ out) {
    int b = blockIdx.x;
    int slot = g_pos[b*Lsz];
    for (int t = threadIdx.x; t < 512; t += blockDim.x)
        out[b*512 + t] = g_HC[(size_t)slot*HCLD + t];
}

// ---------------------------------------------------------------------------
extern "C" void kernel_launch(void* const* d_in, const int* in_sizes, int n_in,
                              void* d_out, int out_size) {
    const float* inp    = (const float*)d_in[0];
    const int*   length = (const int*)  d_in[1];
    const float* word_W = (const float*)d_in[2];
    const float* word_b = (const float*)d_in[3];
    const float* comp_W = (const float*)d_in[4];
    const float* comp_b = (const float*)d_in[5];
    const float* q      = (const float*)d_in[6];
    float* out = (float*)d_out;
    (void)in_sizes; (void)n_in; (void)out_size;

    float *HC = nullptr, *UW = nullptr, *NH = nullptr;
    int *rowmap = nullptr;
    cudaGetSymbolAddress((void**)&HC, g_HC);
    cudaGetSymbolAddress((void**)&UW, g_UW);
    cudaGetSymbolAddress((void**)&NH, g_NH);
    cudaGetSymbolAddress((void**)&rowmap, g_rowmap);

    k_init_pos<<<6, 256>>>();

    // hc = inp @ word_W.T + word_b  -> HC[slot][h|c]
    gemm_nt<64, false><<<dim3(1024/64, NSLOT/64), 256>>>(
        inp, Dsz, word_W, Dsz, word_b, HC, HCLD, Dsz, nullptr);

    // u|w projections for all 1536 leaf nodes (comp_b folded into u half)
    gemm_nt<64, true><<<dim3(5120/64, NSLOT/64), 256>>>(
        HC, HCLD, comp_W, 0, comp_b, UW, UWLD, Hsz, nullptr);

    k_score_all<<<dim3(Lsz-1, Bsz), 256>>>(q);

    for (int i = 0; i < Lsz - 1; i++) {
        k_step<<<Bsz, 256>>>(q, length, i);
        if (i < Lsz - 2) {
            // re-project u|w for the 64 merged nodes (scatter via rowmap)
            gemm_nt<32, true><<<dim3(5120/32, 1), 128>>>(
                NH, Hsz, comp_W, 0, comp_b, UW, UWLD, Hsz, rowmap);
        }
    }

    k_output<<<Bsz, 256>>>(out);
}

// round 7
// speedup vs baseline: 1.1538x; 1.1538x over previous
#include <cuda_runtime.h>
#include <math.h>

// Problem constants
#define Bsz 64
#define Lsz 24
#define Dsz 512
#define Hsz 512
#define NSLOT (Bsz*Lsz)   // 1536 node slots
#define UWLD 5120         // per-slot row: [u(2560) | w(2560)]
#define HCLD 1024         // per-slot row: [h(512) | c(512)]

// Static scratch (no allocations allowed)
__device__ __align__(16) float g_HC[NSLOT*HCLD];   // 6.3 MB
__device__ __align__(16) float g_UW[NSLOT*UWLD];   // 31.5 MB
__device__ __align__(16) float g_NH[Bsz*Hsz];      // merged-node h, compact per batch
__device__ float g_scores[Bsz*Lsz];
__device__ int   g_pos[Bsz*Lsz];                   // logical position -> slot
__device__ int   g_k[Bsz];                         // last merge position (-1 = none)
__device__ int   g_rowmap[Bsz];                    // slot to receive updated u/w (-1 = skip)

__device__ __forceinline__ float sigf(float x) { return 1.0f/(1.0f+expf(-x)); }

// Gate math for pair (slot l, slot r) at hidden dim t.
// v = u_l + w_r  (comp_b already folded into u during the GEMM)
__device__ __forceinline__ void pair_gates(int l, int r, int t, float& nh, float& nc) {
    const float* u = g_UW + (size_t)l*UWLD;
    const float* w = g_UW + (size_t)r*UWLD + 2560;
    float gi  = u[t]        + w[t];
    float gfl = u[512 + t]  + w[512 + t];
    float gfr = u[1024 + t] + w[1024 + t];
    float gu  = u[1536 + t] + w[1536 + t];
    float go  = u[2048 + t] + w[2048 + t];
    float cl  = g_HC[(size_t)l*HCLD + 512 + t];
    float cr  = g_HC[(size_t)r*HCLD + 512 + t];
    nc = cl*sigf(gfl + 1.0f) + cr*sigf(gfr + 1.0f) + tanhf(gu)*sigf(gi);
    nh = sigf(go)*tanhf(nc);
}

// ---------------------------------------------------------------------------
// NT GEMM: C[m,n] = sum_k A[m,k]*B[n,k] (+bias). Tile BMxBN, microtile TMxTN,
// threads = (BM/TM)*(BN/TN). TN must be 4 (float4 epilogue), TM in {4,8}.
// DUAL: virtual B = [comp_W[:, :512] ; comp_W[:, 512:]] stacked (n<2560 -> Wl,
// else Wr), bias applied to first half only (tile-uniform: 2560 % BN == 0).
// rowmap: per-m output row (-1 = skip row).
// ---------------------------------------------------------------------------
template<int BM, int BN, int TM, bool DUAL>
__global__ void __launch_bounds__((BM/TM)*(BN/4))
gemm_nt(const float* __restrict__ A, int lda,
        const float* __restrict__ Bm, int ldb,
        const float* __restrict__ bias,
        float* __restrict__ C, int ldc,
        int K,
        const int* __restrict__ rowmap)
{
    constexpr int BK = 16;
    constexpr int TN = 4;
    constexpr int NTH = (BM/TM)*(BN/TN);
    constexpr int NXT = BN/TN;
    __shared__ float As[BK][BM];
    __shared__ float Bs[BK][BN];
    const int tid = threadIdx.x;
    const int m0 = blockIdx.y * BM;
    const int n0 = blockIdx.x * BN;
    const int tx = tid % NXT;
    const int ty = tid / NXT;
    float acc[TM][TN];
    #pragma unroll
    for (int i = 0; i < TM; i++)
        #pragma unroll
        for (int j = 0; j < TN; j++) acc[i][j] = 0.f;

    for (int k0 = 0; k0 < K; k0 += BK) {
        // load A tile (BM x BK) as float4 along k, stored transposed
        #pragma unroll
        for (int idx = tid; idx < BM*BK/4; idx += NTH) {
            int m  = idx >> 2;          // BK/4 == 4
            int kq = idx & 3;
            float4 a = *(const float4*)(A + (size_t)(m0+m)*lda + k0 + kq*4);
            As[kq*4+0][m] = a.x; As[kq*4+1][m] = a.y;
            As[kq*4+2][m] = a.z; As[kq*4+3][m] = a.w;
        }
        // load B tile (BN x BK)
        #pragma unroll
        for (int idx = tid; idx < BN*BK/4; idx += NTH) {
            int n  = idx >> 2;
            int kq = idx & 3;
            int gn = n0 + n;
            const float* bp;
            if (DUAL)
                bp = (gn < 2560) ? (Bm + (size_t)gn*1024 + k0 + kq*4)
                                 : (Bm + (size_t)(gn-2560)*1024 + 512 + k0 + kq*4);
            else
                bp = Bm + (size_t)gn*ldb + k0 + kq*4;
            float4 bv = *(const float4*)bp;
            Bs[kq*4+0][n] = bv.x; Bs[kq*4+1][n] = bv.y;
            Bs[kq*4+2][n] = bv.z; Bs[kq*4+3][n] = bv.w;
        }
        __syncthreads();
        #pragma unroll
        for (int k = 0; k < BK; k++) {
            float am[TM], bn_[TN];
            #pragma unroll
            for (int q = 0; q < TM/4; q++) {
                float4 av = *(const float4*)&As[k][ty*TM + q*4];
                am[q*4+0] = av.x; am[q*4+1] = av.y;
                am[q*4+2] = av.z; am[q*4+3] = av.w;
            }
            float4 bv = *(const float4*)&Bs[k][tx*TN];
            bn_[0] = bv.x; bn_[1] = bv.y; bn_[2] = bv.z; bn_[3] = bv.w;
            #pragma unroll
            for (int i = 0; i < TM; i++)
                #pragma unroll
                for (int j = 0; j < TN; j++)
                    acc[i][j] += am[i]*bn_[j];
        }
        __syncthreads();
    }

    int gn = n0 + tx*TN;
    float b0 = 0.f, b1 = 0.f, b2 = 0.f, b3 = 0.f;
    if (bias && (!DUAL || gn < 2560)) {
        b0 = bias[gn]; b1 = bias[gn+1]; b2 = bias[gn+2]; b3 = bias[gn+3];
    }
    #pragma unroll
    for (int i = 0; i < TM; i++) {
        int m = m0 + ty*TM + i;
        int orow = rowmap ? rowmap[m] : m;
        if (orow < 0) continue;
        float4 o;
        o.x = acc[i][0] + b0; o.y = acc[i][1] + b1;
        o.z = acc[i][2] + b2; o.w = acc[i][3] + b3;
        *(float4*)(C + (size_t)orow*ldc + gn) = o;
    }
}

// ---------------------------------------------------------------------------
__global__ void k_init_pos() {
    int i = blockIdx.x*blockDim.x + threadIdx.x;
    if (i < Bsz*Lsz) g_pos[i] = i;
}

// Iteration 0: score all 23 adjacent pairs (invalid ones are masked at argmax,
// matching the reference, which also computes them).
__global__ void k_score_all(const float* __restrict__ q) {
    int j = blockIdx.x, b = blockIdx.y;
    int l = g_pos[b*Lsz + j], r = g_pos[b*Lsz + j + 1];
    float part = 0.f;
    for (int t = threadIdx.x; t < 512; t += 256) {
        float nh, nc; pair_gates(l, r, t, nh, nc);
        part += nh * q[t];
    }
    __shared__ float red[8];
    #pragma unroll
    for (int o = 16; o; o >>= 1) part += __shfl_down_sync(0xffffffffu, part, o);
    if ((threadIdx.x & 31) == 0) red[threadIdx.x >> 5] = part;
    __syncthreads();
    if (threadIdx.x == 0) {
        float s = 0.f;
        #pragma unroll
        for (int w = 0; w < 8; w++) s += red[w];
        g_scores[b*Lsz + j] = s;
    }
}

// Fused per-iteration step: rescore the (<=2) pairs invalidated by last merge,
// argmax over valid pairs, merge at k (reusing left child's slot), shift the
// logical pos/scores lists, stage new_h for the u/w update GEMM.
__global__ void k_step(const float* __restrict__ q, const int* __restrict__ length, int iter) {
    int b = blockIdx.x;
    int tid = threadIdx.x;
    __shared__ float red[2][4];
    __shared__ int s_k;
    int nvalid = length[b] - 1 - iter;   // valid pair count this iteration

    if (iter > 0) {
        int kp = g_k[b];                 // previous merge position
        if (kp >= 0) {
            int half = tid >> 7;         // pair selector: kp-1 or kp
            int ht   = tid & 127;
            int jj = kp - 1 + half;
            bool act = (jj >= 0) && (jj < nvalid);  // only valid scores are ever read
            float part = 0.f;
            if (act) {
                int l = g_pos[b*Lsz + jj], r = g_pos[b*Lsz + jj + 1];
                #pragma unroll
                for (int s = 0; s < 4; s++) {
                    int t = ht + s*128;
                    float nh, nc; pair_gates(l, r, t, nh, nc);
                    part += nh * q[t];
                }
            }
            #pragma unroll
            for (int o = 16; o; o >>= 1) part += __shfl_down_sync(0xffffffffu, part, o);
            if ((ht & 31) == 0) red[half][ht >> 5] = part;
            __syncthreads();
            if (ht == 0 && act)
                g_scores[b*Lsz + jj] = red[half][0] + red[half][1] + red[half][2] + red[half][3];
        }
    }
    __syncthreads();

    // argmax with first-index tie-break (matches jnp.argmax)
    if (tid < 32) {
        float v = (tid < nvalid) ? g_scores[b*Lsz + tid] : -1e9f;
        int idx = tid;
        #pragma unroll
        for (int o = 16; o; o >>= 1) {
            float v2 = __shfl_down_sync(0xffffffffu, v, o);
            int  i2  = __shfl_down_sync(0xffffffffu, idx, o);
            if (v2 > v || (v2 == v && i2 < idx)) { v = v2; idx = i2; }
        }
        if (tid == 0) s_k = (nvalid > 0) ? idx : -1;
    }
    __syncthreads();
    int k = s_k;
    if (k < 0) {                                   // done==0: sequence frozen
        if (tid == 0) { g_rowmap[b] = -1; g_k[b] = -1; }
        return;
    }
    int l = g_pos[b*Lsz + k], r = g_pos[b*Lsz + k + 1];
    for (int t = tid; t < 512; t += 256) {
        float nh, nc; pair_gates(l, r, t, nh, nc);
        g_HC[(size_t)l*HCLD + t]       = nh;       // merged node reuses left slot
        g_HC[(size_t)l*HCLD + 512 + t] = nc;
        g_NH[b*512 + t] = nh;                      // staged for update GEMM
    }
    __syncthreads();
    if (tid == 0) {
        g_rowmap[b] = l;
        g_k[b] = k;
        // left-shift logical lists past the removed right child; score[k]/[k-1]
        // become stale but are rescored next iteration iff still valid.
        for (int j = k + 1; j < Lsz - 1; j++) {
            g_pos[b*Lsz + j]    = g_pos[b*Lsz + j + 1];
            g_scores[b*Lsz + j] = g_scores[b*Lsz + j + 1];
        }
    }
}

__global__ void k_output(float* __restrict__ out) {
    int b = blockIdx.x;
    int slot = g_pos[b*Lsz];
    for (int t = threadIdx.x; t < 512; t += blockDim.x)
        out[b*512 + t] = g_HC[(size_t)slot*HCLD + t];
}

// ---------------------------------------------------------------------------
extern "C" void kernel_launch(void* const* d_in, const int* in_sizes, int n_in,
                              void* d_out, int out_size) {
    const float* inp    = (const float*)d_in[0];
    const int*   length = (const int*)  d_in[1];
    const float* word_W = (const float*)d_in[2];
    const float* word_b = (const float*)d_in[3];
    const float* comp_W = (const float*)d_in[4];
    const float* comp_b = (const float*)d_in[5];
    const float* q      = (const float*)d_in[6];
    float* out = (float*)d_out;
    (void)in_sizes; (void)n_in; (void)out_size;

    float *HC = nullptr, *UW = nullptr, *NH = nullptr;
    int *rowmap = nullptr;
    cudaGetSymbolAddress((void**)&HC, g_HC);
    cudaGetSymbolAddress((void**)&UW, g_UW);
    cudaGetSymbolAddress((void**)&NH, g_NH);
    cudaGetSymbolAddress((void**)&rowmap, g_rowmap);

    k_init_pos<<<6, 256>>>();

    // hc = inp @ word_W.T + word_b  -> HC[slot][h|c]
    // 128x64 tile, 8x4 micro, 256 threads
    gemm_nt<128, 64, 8, false><<<dim3(1024/64, NSLOT/128), 256>>>(
        inp, Dsz, word_W, Dsz, word_b, HC, HCLD, Dsz, nullptr);

    // u|w projections for all 1536 leaf nodes (comp_b folded into u half)
    gemm_nt<128, 64, 8, true><<<dim3(5120/64, NSLOT/128), 256>>>(
        HC, HCLD, comp_W, 0, comp_b, UW, UWLD, Hsz, nullptr);

    k_score_all<<<dim3(Lsz-1, Bsz), 256>>>(q);

    for (int i = 0; i < Lsz - 1; i++) {
        k_step<<<Bsz, 256>>>(q, length, i);
        if (i < Lsz - 2) {
            // re-project u|w for the 64 merged nodes (scatter via rowmap).
            // 64x40 tiles -> 128 blocks = one clean wave on 148 SMs (no tail).
            gemm_nt<64, 40, 4, true><<<dim3(5120/40, 1), 160>>>(
                NH, Hsz, comp_W, 0, comp_b, UW, UWLD, Hsz, rowmap);
        }
    }

    k_output<<<Bsz, 256>>>(out);
}